// round 1
// baseline (speedup 1.0000x reference)
#include <cuda_runtime.h>
#include <math_constants.h>

namespace cfg {
constexpr int B = 2, S = 2048, D = 1024, H = 16, HD = 64;
constexpr int MTOT = B * S;                 // 4096
constexpr float SCALE = 0.125f;             // 1/sqrt(64)
}

// Scratch (allocation-free rule => __device__ globals)
__device__ float g_qkv[cfg::MTOT * 3 * cfg::D];   // 48 MB
__device__ float g_att[cfg::MTOT * cfg::D];       // 16 MB

// ---------------------------------------------------------------------------
// C[M,N] = A[M,K] @ B[N,K]^T (+ bias), torch-Linear convention.
// 64x64 block tile, BK=16, 256 threads, 4x4 per thread.
// ---------------------------------------------------------------------------
template <bool HAS_BIAS>
__global__ __launch_bounds__(256) void gemm_nt_kernel(
    const float* __restrict__ A, const float* __restrict__ Bw,
    const float* __restrict__ bias, float* __restrict__ C,
    int M, int N, int K)
{
    constexpr int BM = 64, BN = 64, BK = 16;
    __shared__ float As[BK][BM + 4];
    __shared__ float Bs[BK][BN + 4];

    const int tid = threadIdx.x;
    const int tx = tid & 15, ty = tid >> 4;
    const int m0 = blockIdx.y * BM, n0 = blockIdx.x * BN;
    const int lrow = tid >> 2;            // 0..63
    const int lcol = (tid & 3) << 2;      // 0,4,8,12

    const float* Aptr = A + (size_t)(m0 + lrow) * K + lcol;
    const float* Bptr = Bw + (size_t)(n0 + lrow) * K + lcol;

    float acc[4][4];
#pragma unroll
    for (int i = 0; i < 4; i++)
#pragma unroll
        for (int j = 0; j < 4; j++) acc[i][j] = 0.f;

    for (int k0 = 0; k0 < K; k0 += BK) {
        float4 a4 = *(const float4*)(Aptr + k0);
        float4 b4 = *(const float4*)(Bptr + k0);
        As[lcol + 0][lrow] = a4.x; As[lcol + 1][lrow] = a4.y;
        As[lcol + 2][lrow] = a4.z; As[lcol + 3][lrow] = a4.w;
        Bs[lcol + 0][lrow] = b4.x; Bs[lcol + 1][lrow] = b4.y;
        Bs[lcol + 2][lrow] = b4.z; Bs[lcol + 3][lrow] = b4.w;
        __syncthreads();
#pragma unroll
        for (int k = 0; k < BK; ++k) {
            float a[4], b[4];
            *(float4*)a = *(const float4*)&As[k][ty << 2];
            *(float4*)b = *(const float4*)&Bs[k][tx << 2];
#pragma unroll
            for (int i = 0; i < 4; i++)
#pragma unroll
                for (int j = 0; j < 4; j++)
                    acc[i][j] = fmaf(a[i], b[j], acc[i][j]);
        }
        __syncthreads();
    }

#pragma unroll
    for (int i = 0; i < 4; i++) {
        const int m = m0 + (ty << 2) + i;
        float4 v;
        v.x = acc[i][0]; v.y = acc[i][1]; v.z = acc[i][2]; v.w = acc[i][3];
        if (HAS_BIAS) {
            const float4 bb = *(const float4*)&bias[n0 + (tx << 2)];
            v.x += bb.x; v.y += bb.y; v.z += bb.z; v.w += bb.w;
        }
        *(float4*)&C[(size_t)m * N + n0 + (tx << 2)] = v;
    }
}

// ---------------------------------------------------------------------------
// Flash-style attention. One block per (q-tile of 64, head, batch).
// qkv layout: [b*S+s][3*D] with cols = qkv_idx*1024 + h*64 + d.
// smem: Qst/Kst k-major [64][64], V row-major [64][64], P [64][68].
// Row-softmax stats via shfl within the 4-lane row group.
// ---------------------------------------------------------------------------
constexpr int ATTN_SMEM = (3 * 64 * 64 + 64 * 68) * 4;   // 66560 B

__global__ __launch_bounds__(256) void attn_kernel(
    const float* __restrict__ qkv, float* __restrict__ out)
{
    extern __shared__ float sm[];
    float* Qst = sm;             // Qst[k*64 + row]
    float* Kst = sm + 4096;      // Kst[k*64 + col]
    float* Vs  = sm + 8192;      // Vs[s*64 + d]
    float* Ps  = sm + 12288;     // Ps[row*68 + col]

    const int tid = threadIdx.x;
    const int b = blockIdx.z, h = blockIdx.y;
    const int q0 = blockIdx.x * 64;

    const float* qb = qkv + (size_t)b * cfg::S * (3 * cfg::D) + h * cfg::HD;
    const float* kb = qb + cfg::D;
    const float* vb = qb + 2 * cfg::D;

    const int lrow = tid >> 2;            // 0..63
    const int lc   = (tid & 3) << 4;      // 0,16,32,48

    // Q tile, transposed to k-major
#pragma unroll
    for (int i = 0; i < 16; i += 4) {
        float4 v = *(const float4*)(qb + (size_t)(q0 + lrow) * (3 * cfg::D) + lc + i);
        Qst[(lc + i + 0) * 64 + lrow] = v.x;
        Qst[(lc + i + 1) * 64 + lrow] = v.y;
        Qst[(lc + i + 2) * 64 + lrow] = v.z;
        Qst[(lc + i + 3) * 64 + lrow] = v.w;
    }

    const int tx = tid & 15, ty = tid >> 4;   // S-compute mapping (16x16, 4x4 each)
    const int r  = tid >> 2;                  // row-ownership mapping
    const int c0 = (tid & 3) << 4;            // 16-col slice of hd / of S-row

    float o[16];
#pragma unroll
    for (int c = 0; c < 16; ++c) o[c] = 0.f;
    float m_run = -CUDART_INF_F;
    float l_run = 0.f;

    for (int t = 0; t < cfg::S / 64; ++t) {
        const int s0 = t * 64;
        __syncthreads();   // prior-iter P·V done with Vs before overwrite (also covers Q store on t=0)
#pragma unroll
        for (int i = 0; i < 16; i += 4) {
            float4 kv = *(const float4*)(kb + (size_t)(s0 + lrow) * (3 * cfg::D) + lc + i);
            Kst[(lc + i + 0) * 64 + lrow] = kv.x;
            Kst[(lc + i + 1) * 64 + lrow] = kv.y;
            Kst[(lc + i + 2) * 64 + lrow] = kv.z;
            Kst[(lc + i + 3) * 64 + lrow] = kv.w;
            float4 vv = *(const float4*)(vb + (size_t)(s0 + lrow) * (3 * cfg::D) + lc + i);
            *(float4*)&Vs[lrow * 64 + lc + i] = vv;
        }
        __syncthreads();

        // S = Q K^T
        float acc[4][4];
#pragma unroll
        for (int i = 0; i < 4; i++)
#pragma unroll
            for (int j = 0; j < 4; j++) acc[i][j] = 0.f;
#pragma unroll 8
        for (int k = 0; k < 64; ++k) {
            float a[4], bb[4];
            *(float4*)a  = *(const float4*)&Qst[k * 64 + (ty << 2)];
            *(float4*)bb = *(const float4*)&Kst[k * 64 + (tx << 2)];
#pragma unroll
            for (int i = 0; i < 4; i++)
#pragma unroll
                for (int j = 0; j < 4; j++)
                    acc[i][j] = fmaf(a[i], bb[j], acc[i][j]);
        }
#pragma unroll
        for (int i = 0; i < 4; i++) {
            float4 v;
            v.x = acc[i][0] * cfg::SCALE; v.y = acc[i][1] * cfg::SCALE;
            v.z = acc[i][2] * cfg::SCALE; v.w = acc[i][3] * cfg::SCALE;
            *(float4*)&Ps[((ty << 2) + i) * 68 + (tx << 2)] = v;
        }
        // warp w writes S-rows [8w,8w+8) and owns softmax rows [8w,8w+8): intra-warp
        __syncwarp();

        // online softmax: row r handled by 4 consecutive lanes
        float lmax = -CUDART_INF_F;
#pragma unroll
        for (int c = 0; c < 16; ++c) lmax = fmaxf(lmax, Ps[r * 68 + c0 + c]);
        lmax = fmaxf(lmax, __shfl_xor_sync(0xffffffffu, lmax, 1));
        lmax = fmaxf(lmax, __shfl_xor_sync(0xffffffffu, lmax, 2));
        const float mnew = fmaxf(m_run, lmax);
        const float corr = __expf(m_run - mnew);   // exp(-inf)=0 on first tile
        m_run = mnew;
        l_run *= corr;
#pragma unroll
        for (int c = 0; c < 16; ++c) o[c] *= corr;
        float lsum = 0.f;
#pragma unroll
        for (int c = 0; c < 16; ++c) {
            float p = __expf(Ps[r * 68 + c0 + c] - mnew);
            Ps[r * 68 + c0 + c] = p;
            lsum += p;
        }
        lsum += __shfl_xor_sync(0xffffffffu, lsum, 1);
        lsum += __shfl_xor_sync(0xffffffffu, lsum, 2);
        l_run += lsum;
        __syncwarp();   // P of row r fully written (by this warp) before P·V reads it

        // O += P @ V   (pad 68 -> broadcast reads hit 8 distinct banks)
#pragma unroll 4
        for (int j = 0; j < 64; ++j) {
            const float p = Ps[r * 68 + j];
#pragma unroll
            for (int cc = 0; cc < 16; cc += 4) {
                float4 v = *(const float4*)&Vs[j * 64 + c0 + cc];
                o[cc + 0] = fmaf(p, v.x, o[cc + 0]);
                o[cc + 1] = fmaf(p, v.y, o[cc + 1]);
                o[cc + 2] = fmaf(p, v.z, o[cc + 2]);
                o[cc + 3] = fmaf(p, v.w, o[cc + 3]);
            }
        }
    }

    const float inv = 1.f / l_run;
    float* op = out + (size_t)(b * cfg::S + q0 + r) * cfg::D + h * cfg::HD + c0;
#pragma unroll
    for (int cc = 0; cc < 16; cc += 4) {
        float4 v;
        v.x = o[cc + 0] * inv; v.y = o[cc + 1] * inv;
        v.z = o[cc + 2] * inv; v.w = o[cc + 3] * inv;
        *(float4*)(op + cc) = v;
    }
}

// ---------------------------------------------------------------------------
extern "C" void kernel_launch(void* const* d_in, const int* in_sizes, int n_in,
                              void* d_out, int out_size)
{
    const float* x    = (const float*)d_in[0];   // [2,2048,1024]
    const float* Wqkv = (const float*)d_in[1];   // [3072,1024]
    const float* Wout = (const float*)d_in[2];   // [1024,1024]
    const float* bout = (const float*)d_in[3];   // [1024]
    float* out = (float*)d_out;                  // [2,2048,1024]

    float *qkv = nullptr, *att = nullptr;
    cudaGetSymbolAddress((void**)&qkv, g_qkv);
    cudaGetSymbolAddress((void**)&att, g_att);

    cudaFuncSetAttribute(attn_kernel,
                         cudaFuncAttributeMaxDynamicSharedMemorySize, ATTN_SMEM);

    dim3 blk(256);
    // 1) qkv = x @ W_qkv^T           [4096, 3072]
    gemm_nt_kernel<false><<<dim3(3 * cfg::D / 64, cfg::MTOT / 64), blk>>>(
        x, Wqkv, nullptr, qkv, cfg::MTOT, 3 * cfg::D, cfg::D);
    // 2) flash attention -> g_att    [4096, 1024]
    attn_kernel<<<dim3(cfg::S / 64, cfg::H, cfg::B), blk, ATTN_SMEM>>>(qkv, att);
    // 3) out = att @ W_out^T + b
    gemm_nt_kernel<true><<<dim3(cfg::D / 64, cfg::MTOT / 64), blk>>>(
        att, Wout, bout, out, cfg::MTOT, cfg::D, cfg::D);
}

// round 2
// speedup vs baseline: 1.9856x; 1.9856x over previous
#include <cuda_runtime.h>
#include <math_constants.h>

namespace cfg {
constexpr int B = 2, S = 2048, D = 1024, H = 16, HD = 64;
constexpr int MTOT = B * S;                 // 4096
constexpr float SCALE = 0.125f;             // 1/sqrt(64)
}

// Scratch (allocation-free rule => __device__ globals)
__device__ float g_qkv[cfg::MTOT * 3 * cfg::D];   // 48 MB
__device__ float g_att[cfg::MTOT * cfg::D];       // 16 MB

// ---------------------------------------------------------------------------
// C[M,N] = A[M,K] @ B[N,K]^T (+ bias). 128x128 tile, BK=16, 256 thr, 8x8/thread.
// k-major smem, register-prefetch of next gmem tile.
// ---------------------------------------------------------------------------
template <bool HAS_BIAS>
__global__ __launch_bounds__(256, 2) void gemm_nt_kernel(
    const float* __restrict__ A, const float* __restrict__ Bw,
    const float* __restrict__ bias, float* __restrict__ C,
    int M, int N, int K)
{
    constexpr int BM = 128, BN = 128, BK = 16;
    __shared__ float As[BK][BM + 4];
    __shared__ float Bs[BK][BN + 4];

    const int tid = threadIdx.x;
    const int tx = tid & 15, ty = tid >> 4;
    const int m0 = blockIdx.y * BM, n0 = blockIdx.x * BN;

    const int lrow = tid >> 2;          // 0..63 (second slot: +64)
    const int lkc  = (tid & 3) << 2;    // 0,4,8,12

    const float* Ap  = A  + (size_t)(m0 + lrow) * K + lkc;
    const float* Bp  = Bw + (size_t)(n0 + lrow) * K + lkc;
    const float* Ap2 = Ap + (size_t)64 * K;
    const float* Bp2 = Bp + (size_t)64 * K;

    float4 pa0, pa1, pb0, pb1;

    auto ldg = [&](int k0) {
        pa0 = *(const float4*)(Ap  + k0);
        pa1 = *(const float4*)(Ap2 + k0);
        pb0 = *(const float4*)(Bp  + k0);
        pb1 = *(const float4*)(Bp2 + k0);
    };
    auto sts = [&]() {
        As[lkc + 0][lrow]      = pa0.x; As[lkc + 1][lrow]      = pa0.y;
        As[lkc + 2][lrow]      = pa0.z; As[lkc + 3][lrow]      = pa0.w;
        As[lkc + 0][lrow + 64] = pa1.x; As[lkc + 1][lrow + 64] = pa1.y;
        As[lkc + 2][lrow + 64] = pa1.z; As[lkc + 3][lrow + 64] = pa1.w;
        Bs[lkc + 0][lrow]      = pb0.x; Bs[lkc + 1][lrow]      = pb0.y;
        Bs[lkc + 2][lrow]      = pb0.z; Bs[lkc + 3][lrow]      = pb0.w;
        Bs[lkc + 0][lrow + 64] = pb1.x; Bs[lkc + 1][lrow + 64] = pb1.y;
        Bs[lkc + 2][lrow + 64] = pb1.z; Bs[lkc + 3][lrow + 64] = pb1.w;
    };

    float acc[8][8];
#pragma unroll
    for (int i = 0; i < 8; i++)
#pragma unroll
        for (int j = 0; j < 8; j++) acc[i][j] = 0.f;

    ldg(0); sts(); __syncthreads();

    for (int k0 = 0; k0 < K; k0 += BK) {
        const bool nxt = (k0 + BK) < K;
        if (nxt) ldg(k0 + BK);
#pragma unroll
        for (int k = 0; k < BK; ++k) {
            float a[8], b[8];
            *(float4*)&a[0] = *(const float4*)&As[k][8 * ty];
            *(float4*)&a[4] = *(const float4*)&As[k][8 * ty + 4];
            *(float4*)&b[0] = *(const float4*)&Bs[k][8 * tx];
            *(float4*)&b[4] = *(const float4*)&Bs[k][8 * tx + 4];
#pragma unroll
            for (int i = 0; i < 8; i++)
#pragma unroll
                for (int j = 0; j < 8; j++)
                    acc[i][j] = fmaf(a[i], b[j], acc[i][j]);
        }
        __syncthreads();
        if (nxt) { sts(); __syncthreads(); }
    }

#pragma unroll
    for (int i = 0; i < 8; i++) {
        float* crow = &C[(size_t)(m0 + 8 * ty + i) * N + n0 + 8 * tx];
        float4 v0, v1;
        v0.x = acc[i][0]; v0.y = acc[i][1]; v0.z = acc[i][2]; v0.w = acc[i][3];
        v1.x = acc[i][4]; v1.y = acc[i][5]; v1.z = acc[i][6]; v1.w = acc[i][7];
        if (HAS_BIAS) {
            const float4 b0 = *(const float4*)&bias[n0 + 8 * tx];
            const float4 b1 = *(const float4*)&bias[n0 + 8 * tx + 4];
            v0.x += b0.x; v0.y += b0.y; v0.z += b0.z; v0.w += b0.w;
            v1.x += b1.x; v1.y += b1.y; v1.z += b1.z; v1.w += b1.w;
        }
        *(float4*)crow       = v0;
        *(float4*)(crow + 4) = v1;
    }
}

// ---------------------------------------------------------------------------
// Flash attention, 64q x 64k tiles, 256 threads.
// S = QK^T as 4x4-tile GEMM; softmax pass writes exp(P) TRANSPOSED (Pt[key][row])
// so PV is also a 4x4-tile GEMM (2 LDS.128 + 16 FFMA per k).
// Row stats warp-local; corr / l broadcast via shfl.
// smem floats: Qst[64*68] Kst[64*68] Vs[64*80] Ps[64*68] Pt[64*68]
// ---------------------------------------------------------------------------
constexpr int PSTR = 68, VSTR = 80;
constexpr int OFF_Q = 0, OFF_K = 4352, OFF_V = 8704, OFF_P = 13824, OFF_PT = 18176;
constexpr int ATTN_SMEM = 22528 * 4;   // 90112 B

__global__ __launch_bounds__(256, 2) void attn_kernel(
    const float* __restrict__ qkv, float* __restrict__ out)
{
    extern __shared__ float sm[];
    float* Qst = sm + OFF_Q;     // [d][row] stride 68
    float* Kst = sm + OFF_K;     // [d][col] stride 68
    float* Vs  = sm + OFF_V;     // [key][d] stride 80
    float* Ps  = sm + OFF_P;     // [row][key] stride 68
    float* Pt  = sm + OFF_PT;    // [key][row] stride 68

    const int tid = threadIdx.x;
    const int b = blockIdx.z, h = blockIdx.y;
    const int q0 = blockIdx.x * 64;
    const int tx = tid & 15, ty = tid >> 4;
    const int lane = tid & 31;

    const float* qb = qkv + (size_t)b * cfg::S * 3072 + h * cfg::HD;
    const float* kb = qb + cfg::D;
    const float* vb = qb + 2 * cfg::D;

    const int lrow = tid >> 2;          // 0..63
    const int lq   = (tid & 3) << 2;    // 0,4,8,12

    // Q tile -> Qst (d-major)
#pragma unroll
    for (int c4 = 0; c4 < 4; c4++) {
        const int col = lq + 16 * c4;
        float4 v = *(const float4*)(qb + (size_t)(q0 + lrow) * 3072 + col);
        Qst[(col + 0) * PSTR + lrow] = v.x;
        Qst[(col + 1) * PSTR + lrow] = v.y;
        Qst[(col + 2) * PSTR + lrow] = v.z;
        Qst[(col + 3) * PSTR + lrow] = v.w;
    }

    float o[4][4];
#pragma unroll
    for (int i = 0; i < 4; i++)
#pragma unroll
        for (int j = 0; j < 4; j++) o[i][j] = 0.f;

    const int r  = tid >> 2;   // stats row
    const int qc = tid & 3;    // stats col phase (cols qc+4i)
    float m_run = -CUDART_INF_F, l_run = 0.f;

    for (int t = 0; t < cfg::S / 64; ++t) {
        const int s0 = t * 64;
        __syncthreads();   // Vs/Kst safe to overwrite
#pragma unroll
        for (int c4 = 0; c4 < 4; c4++) {
            const int col = lq + 16 * c4;
            float4 kv = *(const float4*)(kb + (size_t)(s0 + lrow) * 3072 + col);
            Kst[(col + 0) * PSTR + lrow] = kv.x;
            Kst[(col + 1) * PSTR + lrow] = kv.y;
            Kst[(col + 2) * PSTR + lrow] = kv.z;
            Kst[(col + 3) * PSTR + lrow] = kv.w;
            float4 vv = *(const float4*)(vb + (size_t)(s0 + lrow) * 3072 + col);
            *(float4*)&Vs[lrow * VSTR + col] = vv;
        }
        __syncthreads();

        // S = Q K^T  (4x4 per thread)
        float acc[4][4];
#pragma unroll
        for (int i = 0; i < 4; i++)
#pragma unroll
            for (int j = 0; j < 4; j++) acc[i][j] = 0.f;
#pragma unroll 8
        for (int k = 0; k < 64; ++k) {
            float4 a  = *(const float4*)&Qst[k * PSTR + 4 * ty];
            float4 bb = *(const float4*)&Kst[k * PSTR + 4 * tx];
            acc[0][0] = fmaf(a.x, bb.x, acc[0][0]); acc[0][1] = fmaf(a.x, bb.y, acc[0][1]);
            acc[0][2] = fmaf(a.x, bb.z, acc[0][2]); acc[0][3] = fmaf(a.x, bb.w, acc[0][3]);
            acc[1][0] = fmaf(a.y, bb.x, acc[1][0]); acc[1][1] = fmaf(a.y, bb.y, acc[1][1]);
            acc[1][2] = fmaf(a.y, bb.z, acc[1][2]); acc[1][3] = fmaf(a.y, bb.w, acc[1][3]);
            acc[2][0] = fmaf(a.z, bb.x, acc[2][0]); acc[2][1] = fmaf(a.z, bb.y, acc[2][1]);
            acc[2][2] = fmaf(a.z, bb.z, acc[2][2]); acc[2][3] = fmaf(a.z, bb.w, acc[2][3]);
            acc[3][0] = fmaf(a.w, bb.x, acc[3][0]); acc[3][1] = fmaf(a.w, bb.y, acc[3][1]);
            acc[3][2] = fmaf(a.w, bb.z, acc[3][2]); acc[3][3] = fmaf(a.w, bb.w, acc[3][3]);
        }
#pragma unroll
        for (int i = 0; i < 4; i++) {
            float4 v;
            v.x = acc[i][0] * cfg::SCALE; v.y = acc[i][1] * cfg::SCALE;
            v.z = acc[i][2] * cfg::SCALE; v.w = acc[i][3] * cfg::SCALE;
            *(float4*)&Ps[(4 * ty + i) * PSTR + 4 * tx] = v;
        }
        __syncwarp();   // warp w wrote rows 8w..8w+7 == rows it owns for stats

        // online softmax stats for row r (4 lanes, strided cols qc+4i)
        float pv[16];
        float vmax = -CUDART_INF_F;
#pragma unroll
        for (int i = 0; i < 16; i++) {
            pv[i] = Ps[r * PSTR + qc + 4 * i];
            vmax = fmaxf(vmax, pv[i]);
        }
        vmax = fmaxf(vmax, __shfl_xor_sync(0xffffffffu, vmax, 1));
        vmax = fmaxf(vmax, __shfl_xor_sync(0xffffffffu, vmax, 2));
        const float mnew = fmaxf(m_run, vmax);
        const float corr = __expf(m_run - mnew);
        m_run = mnew;
        float lsum = 0.f;
#pragma unroll
        for (int i = 0; i < 16; i++) {
            const float p = __expf(pv[i] - mnew);
            lsum += p;
            Pt[(qc + 4 * i) * PSTR + r] = p;   // transposed store
        }
        lsum += __shfl_xor_sync(0xffffffffu, lsum, 1);
        lsum += __shfl_xor_sync(0xffffffffu, lsum, 2);
        l_run = l_run * corr + lsum;
        __syncwarp();   // Pt rows of this warp ready

        // fetch corr for my 4 output rows (all within my warp)
        float corr4[4];
#pragma unroll
        for (int i = 0; i < 4; i++)
            corr4[i] = __shfl_sync(0xffffffffu, corr, (lane & 16) | (i << 2));
#pragma unroll
        for (int i = 0; i < 4; i++)
#pragma unroll
            for (int j = 0; j < 4; j++) o[i][j] *= corr4[i];

        // O += P @ V  (4x4 per thread)
#pragma unroll 8
        for (int j = 0; j < 64; ++j) {
            float4 ap = *(const float4*)&Pt[j * PSTR + 4 * ty];
            float4 bv = *(const float4*)&Vs[j * VSTR + 4 * tx];
            o[0][0] = fmaf(ap.x, bv.x, o[0][0]); o[0][1] = fmaf(ap.x, bv.y, o[0][1]);
            o[0][2] = fmaf(ap.x, bv.z, o[0][2]); o[0][3] = fmaf(ap.x, bv.w, o[0][3]);
            o[1][0] = fmaf(ap.y, bv.x, o[1][0]); o[1][1] = fmaf(ap.y, bv.y, o[1][1]);
            o[1][2] = fmaf(ap.y, bv.z, o[1][2]); o[1][3] = fmaf(ap.y, bv.w, o[1][3]);
            o[2][0] = fmaf(ap.z, bv.x, o[2][0]); o[2][1] = fmaf(ap.z, bv.y, o[2][1]);
            o[2][2] = fmaf(ap.z, bv.z, o[2][2]); o[2][3] = fmaf(ap.z, bv.w, o[2][3]);
            o[3][0] = fmaf(ap.w, bv.x, o[3][0]); o[3][1] = fmaf(ap.w, bv.y, o[3][1]);
            o[3][2] = fmaf(ap.w, bv.z, o[3][2]); o[3][3] = fmaf(ap.w, bv.w, o[3][3]);
        }
    }

    float linv[4];
#pragma unroll
    for (int i = 0; i < 4; i++)
        linv[i] = 1.f / __shfl_sync(0xffffffffu, l_run, (lane & 16) | (i << 2));

#pragma unroll
    for (int i = 0; i < 4; i++) {
        float4 v;
        v.x = o[i][0] * linv[i]; v.y = o[i][1] * linv[i];
        v.z = o[i][2] * linv[i]; v.w = o[i][3] * linv[i];
        *(float4*)&out[(size_t)(b * cfg::S + q0 + 4 * ty + i) * cfg::D + h * cfg::HD + 4 * tx] = v;
    }
}

// ---------------------------------------------------------------------------
extern "C" void kernel_launch(void* const* d_in, const int* in_sizes, int n_in,
                              void* d_out, int out_size)
{
    const float* x    = (const float*)d_in[0];   // [2,2048,1024]
    const float* Wqkv = (const float*)d_in[1];   // [3072,1024]
    const float* Wout = (const float*)d_in[2];   // [1024,1024]
    const float* bout = (const float*)d_in[3];   // [1024]
    float* out = (float*)d_out;                  // [2,2048,1024]

    float *qkv = nullptr, *att = nullptr;
    cudaGetSymbolAddress((void**)&qkv, g_qkv);
    cudaGetSymbolAddress((void**)&att, g_att);

    cudaFuncSetAttribute(attn_kernel,
                         cudaFuncAttributeMaxDynamicSharedMemorySize, ATTN_SMEM);

    dim3 blk(256);
    // 1) qkv = x @ W_qkv^T           [4096, 3072]
    gemm_nt_kernel<false><<<dim3(3 * cfg::D / 128, cfg::MTOT / 128), blk>>>(
        x, Wqkv, nullptr, qkv, cfg::MTOT, 3 * cfg::D, cfg::D);
    // 2) flash attention -> g_att    [4096, 1024]
    attn_kernel<<<dim3(cfg::S / 64, cfg::H, cfg::B), blk, ATTN_SMEM>>>(qkv, att);
    // 3) out = att @ W_out^T + b
    gemm_nt_kernel<true><<<dim3(cfg::D / 128, cfg::MTOT / 128), blk>>>(
        att, Wout, bout, out, cfg::MTOT, cfg::D, cfg::D);
}

// round 4
// speedup vs baseline: 2.7760x; 1.3981x over previous
#include <cuda_runtime.h>
#include <math_constants.h>
#include <cstdint>

namespace cfg {
constexpr int B = 2, S = 2048, D = 1024, H = 16, HD = 64;
constexpr int MTOT = B * S;                 // 4096
constexpr float SCALE = 0.125f;             // 1/sqrt(64)
}

// Scratch (allocation-free rule => __device__ globals)
__device__ float g_qkv[cfg::MTOT * 3 * cfg::D];   // 48 MB
__device__ float g_att[cfg::MTOT * cfg::D];       // 16 MB

// ======================= mma.sync tf32 helpers (sm_80+ PTX) ================
__device__ __forceinline__ uint32_t f2tf32(float f) {
    uint32_t u;
    asm("cvt.rna.tf32.f32 %0, %1;" : "=r"(u) : "f"(f));
    return u;
}
__device__ __forceinline__ void mma_tf32_16x8x8(
    float& c0, float& c1, float& c2, float& c3,
    uint32_t a0, uint32_t a1, uint32_t a2, uint32_t a3,
    uint32_t b0, uint32_t b1)
{
    asm volatile(
        "mma.sync.aligned.m16n8k8.row.col.f32.tf32.tf32.f32 "
        "{%0,%1,%2,%3}, {%4,%5,%6,%7}, {%8,%9}, {%0,%1,%2,%3};\n"
        : "+f"(c0), "+f"(c1), "+f"(c2), "+f"(c3)
        : "r"(a0), "r"(a1), "r"(a2), "r"(a3), "r"(b0), "r"(b1));
}

// ---------------------------------------------------------------------------
// C[M,N] = A[M,K] @ B[N,K]^T (+ bias) via mma.sync tf32.
// 128x128 block tile, BK=32, 256 threads (8 warps), warp tile 64x32.
// Smem fragment layout: [row][k] stride 36 words -> (4*row + k) % 32 banks,
// conflict-free for all a/b fragment loads. Values pre-rounded to tf32 (RNA).
// ---------------------------------------------------------------------------
constexpr int ASTR = 36;   // smem row stride in words

template <bool HAS_BIAS>
__global__ __launch_bounds__(256) void gemm_mma_kernel(
    const float* __restrict__ A, const float* __restrict__ Bw,
    const float* __restrict__ bias, float* __restrict__ C,
    int M, int N, int K)
{
    __shared__ float As[128 * ASTR];   // 18432 B
    __shared__ float Bs[128 * ASTR];   // 18432 B

    const int tid = threadIdx.x, wid = tid >> 5, lane = tid & 31;
    const int warp_m = wid >> 2, warp_n = wid & 3;   // 2 x 4 warp grid
    const int m0 = blockIdx.y * 128, n0 = blockIdx.x * 128;

    const int r0 = tid >> 3;          // 0..31 (+32*i)
    const int c4 = tid & 7;           // float4 slot along k
    const float* Ap = A  + (size_t)(m0 + r0) * K + c4 * 4;
    const float* Bp = Bw + (size_t)(n0 + r0) * K + c4 * 4;

    float4 pa[4], pb[4];
    auto ldg = [&](int kc) {
#pragma unroll
        for (int i = 0; i < 4; i++) {
            pa[i] = *(const float4*)(Ap + kc + (size_t)(32 * i) * K);
            pb[i] = *(const float4*)(Bp + kc + (size_t)(32 * i) * K);
        }
    };
    auto sts = [&]() {
#pragma unroll
        for (int i = 0; i < 4; i++) {
            uint32_t* as = (uint32_t*)&As[(r0 + 32 * i) * ASTR + 4 * c4];
            uint32_t* bs = (uint32_t*)&Bs[(r0 + 32 * i) * ASTR + 4 * c4];
            uint4 av, bv;
            av.x = f2tf32(pa[i].x); av.y = f2tf32(pa[i].y);
            av.z = f2tf32(pa[i].z); av.w = f2tf32(pa[i].w);
            bv.x = f2tf32(pb[i].x); bv.y = f2tf32(pb[i].y);
            bv.z = f2tf32(pb[i].z); bv.w = f2tf32(pb[i].w);
            *(uint4*)as = av;
            *(uint4*)bs = bv;
        }
    };

    float acc[4][4][4];
#pragma unroll
    for (int mt = 0; mt < 4; mt++)
#pragma unroll
        for (int nt = 0; nt < 4; nt++)
#pragma unroll
            for (int r = 0; r < 4; r++) acc[mt][nt][r] = 0.f;

    const int gid = lane >> 2;        // 0..7
    const int qid = lane & 3;         // 0..3
    const uint32_t* Asu = (const uint32_t*)As;
    const uint32_t* Bsu = (const uint32_t*)Bs;

    const int nchunk = K / 32;
    ldg(0); sts(); __syncthreads();

    for (int c = 0; c < nchunk; ++c) {
        const bool nxt = (c + 1) < nchunk;
        if (nxt) ldg(32 * (c + 1));
#pragma unroll
        for (int kk = 0; kk < 4; kk++) {
            const int k0 = 8 * kk + qid;
            uint32_t af[4][4], bf[4][2];
#pragma unroll
            for (int mt = 0; mt < 4; mt++) {
                const int m = 64 * warp_m + 16 * mt + gid;
                af[mt][0] = Asu[m * ASTR + k0];
                af[mt][1] = Asu[(m + 8) * ASTR + k0];
                af[mt][2] = Asu[m * ASTR + k0 + 4];
                af[mt][3] = Asu[(m + 8) * ASTR + k0 + 4];
            }
#pragma unroll
            for (int nt = 0; nt < 4; nt++) {
                const int n = 32 * warp_n + 8 * nt + gid;
                bf[nt][0] = Bsu[n * ASTR + k0];
                bf[nt][1] = Bsu[n * ASTR + k0 + 4];
            }
#pragma unroll
            for (int mt = 0; mt < 4; mt++)
#pragma unroll
                for (int nt = 0; nt < 4; nt++)
                    mma_tf32_16x8x8(acc[mt][nt][0], acc[mt][nt][1],
                                    acc[mt][nt][2], acc[mt][nt][3],
                                    af[mt][0], af[mt][1], af[mt][2], af[mt][3],
                                    bf[nt][0], bf[nt][1]);
        }
        __syncthreads();
        if (nxt) { sts(); __syncthreads(); }
    }

    // epilogue: c0,c1 -> (row, 2q/2q+1); c2,c3 -> (row+8, ...)
#pragma unroll
    for (int nt = 0; nt < 4; nt++) {
        const int col = n0 + 32 * warp_n + 8 * nt + 2 * qid;
        float2 badd = make_float2(0.f, 0.f);
        if (HAS_BIAS) badd = *(const float2*)&bias[col];
#pragma unroll
        for (int mt = 0; mt < 4; mt++) {
            const int row = m0 + 64 * warp_m + 16 * mt + gid;
            float2 v0 = make_float2(acc[mt][nt][0] + badd.x, acc[mt][nt][1] + badd.y);
            float2 v1 = make_float2(acc[mt][nt][2] + badd.x, acc[mt][nt][3] + badd.y);
            *(float2*)&C[(size_t)row * N + col]       = v0;
            *(float2*)&C[(size_t)(row + 8) * N + col] = v1;
        }
    }
}

// ---------------------------------------------------------------------------
// Flash attention (fp32 CUDA cores) — unchanged from R2 (passing, 926us).
// ---------------------------------------------------------------------------
constexpr int PSTR = 68, VSTR = 80;
constexpr int OFF_Q = 0, OFF_K = 4352, OFF_V = 8704, OFF_P = 13824, OFF_PT = 18176;
constexpr int ATTN_SMEM = 22528 * 4;   // 90112 B

__global__ __launch_bounds__(256, 2) void attn_kernel(
    const float* __restrict__ qkv, float* __restrict__ out)
{
    extern __shared__ float sm[];
    float* Qst = sm + OFF_Q;
    float* Kst = sm + OFF_K;
    float* Vs  = sm + OFF_V;
    float* Ps  = sm + OFF_P;
    float* Pt  = sm + OFF_PT;

    const int tid = threadIdx.x;
    const int b = blockIdx.z, h = blockIdx.y;
    const int q0 = blockIdx.x * 64;
    const int tx = tid & 15, ty = tid >> 4;
    const int lane = tid & 31;

    const float* qb = qkv + (size_t)b * cfg::S * 3072 + h * cfg::HD;
    const float* kb = qb + cfg::D;
    const float* vb = qb + 2 * cfg::D;

    const int lrow = tid >> 2;
    const int lq   = (tid & 3) << 2;

#pragma unroll
    for (int c4 = 0; c4 < 4; c4++) {
        const int col = lq + 16 * c4;
        float4 v = *(const float4*)(qb + (size_t)(q0 + lrow) * 3072 + col);
        Qst[(col + 0) * PSTR + lrow] = v.x;
        Qst[(col + 1) * PSTR + lrow] = v.y;
        Qst[(col + 2) * PSTR + lrow] = v.z;
        Qst[(col + 3) * PSTR + lrow] = v.w;
    }

    float o[4][4];
#pragma unroll
    for (int i = 0; i < 4; i++)
#pragma unroll
        for (int j = 0; j < 4; j++) o[i][j] = 0.f;

    const int r  = tid >> 2;
    const int qc = tid & 3;
    float m_run = -CUDART_INF_F, l_run = 0.f;

    for (int t = 0; t < cfg::S / 64; ++t) {
        const int s0 = t * 64;
        __syncthreads();
#pragma unroll
        for (int c4 = 0; c4 < 4; c4++) {
            const int col = lq + 16 * c4;
            float4 kv = *(const float4*)(kb + (size_t)(s0 + lrow) * 3072 + col);
            Kst[(col + 0) * PSTR + lrow] = kv.x;
            Kst[(col + 1) * PSTR + lrow] = kv.y;
            Kst[(col + 2) * PSTR + lrow] = kv.z;
            Kst[(col + 3) * PSTR + lrow] = kv.w;
            float4 vv = *(const float4*)(vb + (size_t)(s0 + lrow) * 3072 + col);
            *(float4*)&Vs[lrow * VSTR + col] = vv;
        }
        __syncthreads();

        float acc[4][4];
#pragma unroll
        for (int i = 0; i < 4; i++)
#pragma unroll
            for (int j = 0; j < 4; j++) acc[i][j] = 0.f;
#pragma unroll 8
        for (int k = 0; k < 64; ++k) {
            float4 a  = *(const float4*)&Qst[k * PSTR + 4 * ty];
            float4 bb = *(const float4*)&Kst[k * PSTR + 4 * tx];
            acc[0][0] = fmaf(a.x, bb.x, acc[0][0]); acc[0][1] = fmaf(a.x, bb.y, acc[0][1]);
            acc[0][2] = fmaf(a.x, bb.z, acc[0][2]); acc[0][3] = fmaf(a.x, bb.w, acc[0][3]);
            acc[1][0] = fmaf(a.y, bb.x, acc[1][0]); acc[1][1] = fmaf(a.y, bb.y, acc[1][1]);
            acc[1][2] = fmaf(a.y, bb.z, acc[1][2]); acc[1][3] = fmaf(a.y, bb.w, acc[1][3]);
            acc[2][0] = fmaf(a.z, bb.x, acc[2][0]); acc[2][1] = fmaf(a.z, bb.y, acc[2][1]);
            acc[2][2] = fmaf(a.z, bb.z, acc[2][2]); acc[2][3] = fmaf(a.z, bb.w, acc[2][3]);
            acc[3][0] = fmaf(a.w, bb.x, acc[3][0]); acc[3][1] = fmaf(a.w, bb.y, acc[3][1]);
            acc[3][2] = fmaf(a.w, bb.z, acc[3][2]); acc[3][3] = fmaf(a.w, bb.w, acc[3][3]);
        }
#pragma unroll
        for (int i = 0; i < 4; i++) {
            float4 v;
            v.x = acc[i][0] * cfg::SCALE; v.y = acc[i][1] * cfg::SCALE;
            v.z = acc[i][2] * cfg::SCALE; v.w = acc[i][3] * cfg::SCALE;
            *(float4*)&Ps[(4 * ty + i) * PSTR + 4 * tx] = v;
        }
        __syncwarp();

        float pv[16];
        float vmax = -CUDART_INF_F;
#pragma unroll
        for (int i = 0; i < 16; i++) {
            pv[i] = Ps[r * PSTR + qc + 4 * i];
            vmax = fmaxf(vmax, pv[i]);
        }
        vmax = fmaxf(vmax, __shfl_xor_sync(0xffffffffu, vmax, 1));
        vmax = fmaxf(vmax, __shfl_xor_sync(0xffffffffu, vmax, 2));
        const float mnew = fmaxf(m_run, vmax);
        const float corr = __expf(m_run - mnew);
        m_run = mnew;
        float lsum = 0.f;
#pragma unroll
        for (int i = 0; i < 16; i++) {
            const float p = __expf(pv[i] - mnew);
            lsum += p;
            Pt[(qc + 4 * i) * PSTR + r] = p;
        }
        lsum += __shfl_xor_sync(0xffffffffu, lsum, 1);
        lsum += __shfl_xor_sync(0xffffffffu, lsum, 2);
        l_run = l_run * corr + lsum;
        __syncwarp();

        float corr4[4];
#pragma unroll
        for (int i = 0; i < 4; i++)
            corr4[i] = __shfl_sync(0xffffffffu, corr, (lane & 16) | (i << 2));
#pragma unroll
        for (int i = 0; i < 4; i++)
#pragma unroll
            for (int j = 0; j < 4; j++) o[i][j] *= corr4[i];

#pragma unroll 8
        for (int j = 0; j < 64; ++j) {
            float4 ap = *(const float4*)&Pt[j * PSTR + 4 * ty];
            float4 bv = *(const float4*)&Vs[j * VSTR + 4 * tx];
            o[0][0] = fmaf(ap.x, bv.x, o[0][0]); o[0][1] = fmaf(ap.x, bv.y, o[0][1]);
            o[0][2] = fmaf(ap.x, bv.z, o[0][2]); o[0][3] = fmaf(ap.x, bv.w, o[0][3]);
            o[1][0] = fmaf(ap.y, bv.x, o[1][0]); o[1][1] = fmaf(ap.y, bv.y, o[1][1]);
            o[1][2] = fmaf(ap.y, bv.z, o[1][2]); o[1][3] = fmaf(ap.y, bv.w, o[1][3]);
            o[2][0] = fmaf(ap.z, bv.x, o[2][0]); o[2][1] = fmaf(ap.z, bv.y, o[2][1]);
            o[2][2] = fmaf(ap.z, bv.z, o[2][2]); o[2][3] = fmaf(ap.z, bv.w, o[2][3]);
            o[3][0] = fmaf(ap.w, bv.x, o[3][0]); o[3][1] = fmaf(ap.w, bv.y, o[3][1]);
            o[3][2] = fmaf(ap.w, bv.z, o[3][2]); o[3][3] = fmaf(ap.w, bv.w, o[3][3]);
        }
    }

    float linv[4];
#pragma unroll
    for (int i = 0; i < 4; i++)
        linv[i] = 1.f / __shfl_sync(0xffffffffu, l_run, (lane & 16) | (i << 2));

#pragma unroll
    for (int i = 0; i < 4; i++) {
        float4 v;
        v.x = o[i][0] * linv[i]; v.y = o[i][1] * linv[i];
        v.z = o[i][2] * linv[i]; v.w = o[i][3] * linv[i];
        *(float4*)&out[(size_t)(b * cfg::S + q0 + 4 * ty + i) * cfg::D + h * cfg::HD + 4 * tx] = v;
    }
}

// ---------------------------------------------------------------------------
extern "C" void kernel_launch(void* const* d_in, const int* in_sizes, int n_in,
                              void* d_out, int out_size)
{
    const float* x    = (const float*)d_in[0];   // [2,2048,1024]
    const float* Wqkv = (const float*)d_in[1];   // [3072,1024]
    const float* Wout = (const float*)d_in[2];   // [1024,1024]
    const float* bout = (const float*)d_in[3];   // [1024]
    float* out = (float*)d_out;                  // [2,2048,1024]

    float *qkv = nullptr, *att = nullptr;
    cudaGetSymbolAddress((void**)&qkv, g_qkv);
    cudaGetSymbolAddress((void**)&att, g_att);

    cudaFuncSetAttribute(attn_kernel,
                         cudaFuncAttributeMaxDynamicSharedMemorySize, ATTN_SMEM);

    dim3 blk(256);
    // 1) qkv = x @ W_qkv^T           [4096, 3072]
    gemm_mma_kernel<false><<<dim3(3 * cfg::D / 128, cfg::MTOT / 128), blk>>>(
        x, Wqkv, nullptr, qkv, cfg::MTOT, 3 * cfg::D, cfg::D);
    // 2) flash attention -> g_att    [4096, 1024]
    attn_kernel<<<dim3(cfg::S / 64, cfg::H, cfg::B), blk, ATTN_SMEM>>>(qkv, att);
    // 3) out = att @ W_out^T + b
    gemm_mma_kernel<true><<<dim3(cfg::D / 128, cfg::MTOT / 128), blk>>>(
        att, Wout, bout, out, cfg::MTOT, cfg::D, cfg::D);
}

// round 7
// speedup vs baseline: 4.8394x; 1.7433x over previous
#include <cuda_runtime.h>
#include <math_constants.h>
#include <cstdint>

namespace cfg {
constexpr int B = 2, S = 2048, D = 1024, H = 16, HD = 64;
constexpr int MTOT = B * S;                 // 4096
constexpr float SCALE = 0.125f;             // 1/sqrt(64)
}

// Scratch (allocation-free rule => __device__ globals)
__device__ float g_qkv[cfg::MTOT * 3 * cfg::D];   // 48 MB
__device__ float g_att[cfg::MTOT * cfg::D];       // 16 MB

// ======================= mma.sync tf32 helpers (sm_80+ PTX) ================
__device__ __forceinline__ uint32_t f2tf32(float f) {
    uint32_t u;
    asm("cvt.rna.tf32.f32 %0, %1;" : "=r"(u) : "f"(f));
    return u;
}
__device__ __forceinline__ void mma_tf32_16x8x8(
    float& c0, float& c1, float& c2, float& c3,
    uint32_t a0, uint32_t a1, uint32_t a2, uint32_t a3,
    uint32_t b0, uint32_t b1)
{
    asm volatile(
        "mma.sync.aligned.m16n8k8.row.col.f32.tf32.tf32.f32 "
        "{%0,%1,%2,%3}, {%4,%5,%6,%7}, {%8,%9}, {%0,%1,%2,%3};\n"
        : "+f"(c0), "+f"(c1), "+f"(c2), "+f"(c3)
        : "r"(a0), "r"(a1), "r"(a2), "r"(a3), "r"(b0), "r"(b1));
}

// ---------------------------------------------------------------------------
// C[M,N] = A[M,K] @ B[N,K]^T (+ bias) via mma.sync tf32.  (unchanged from R4)
// ---------------------------------------------------------------------------
constexpr int ASTR = 36;   // smem row stride in words

template <bool HAS_BIAS>
__global__ __launch_bounds__(256) void gemm_mma_kernel(
    const float* __restrict__ A, const float* __restrict__ Bw,
    const float* __restrict__ bias, float* __restrict__ C,
    int M, int N, int K)
{
    __shared__ float As[128 * ASTR];
    __shared__ float Bs[128 * ASTR];

    const int tid = threadIdx.x, wid = tid >> 5, lane = tid & 31;
    const int warp_m = wid >> 2, warp_n = wid & 3;
    const int m0 = blockIdx.y * 128, n0 = blockIdx.x * 128;

    const int r0 = tid >> 3;
    const int c4 = tid & 7;
    const float* Ap = A  + (size_t)(m0 + r0) * K + c4 * 4;
    const float* Bp = Bw + (size_t)(n0 + r0) * K + c4 * 4;

    float4 pa[4], pb[4];
    auto ldg = [&](int kc) {
#pragma unroll
        for (int i = 0; i < 4; i++) {
            pa[i] = *(const float4*)(Ap + kc + (size_t)(32 * i) * K);
            pb[i] = *(const float4*)(Bp + kc + (size_t)(32 * i) * K);
        }
    };
    auto sts = [&]() {
#pragma unroll
        for (int i = 0; i < 4; i++) {
            uint32_t* as = (uint32_t*)&As[(r0 + 32 * i) * ASTR + 4 * c4];
            uint32_t* bs = (uint32_t*)&Bs[(r0 + 32 * i) * ASTR + 4 * c4];
            uint4 av, bv;
            av.x = f2tf32(pa[i].x); av.y = f2tf32(pa[i].y);
            av.z = f2tf32(pa[i].z); av.w = f2tf32(pa[i].w);
            bv.x = f2tf32(pb[i].x); bv.y = f2tf32(pb[i].y);
            bv.z = f2tf32(pb[i].z); bv.w = f2tf32(pb[i].w);
            *(uint4*)as = av;
            *(uint4*)bs = bv;
        }
    };

    float acc[4][4][4];
#pragma unroll
    for (int mt = 0; mt < 4; mt++)
#pragma unroll
        for (int nt = 0; nt < 4; nt++)
#pragma unroll
            for (int r = 0; r < 4; r++) acc[mt][nt][r] = 0.f;

    const int gid = lane >> 2;
    const int qid = lane & 3;
    const uint32_t* Asu = (const uint32_t*)As;
    const uint32_t* Bsu = (const uint32_t*)Bs;

    const int nchunk = K / 32;
    ldg(0); sts(); __syncthreads();

    for (int c = 0; c < nchunk; ++c) {
        const bool nxt = (c + 1) < nchunk;
        if (nxt) ldg(32 * (c + 1));
#pragma unroll
        for (int kk = 0; kk < 4; kk++) {
            const int k0 = 8 * kk + qid;
            uint32_t af[4][4], bf[4][2];
#pragma unroll
            for (int mt = 0; mt < 4; mt++) {
                const int m = 64 * warp_m + 16 * mt + gid;
                af[mt][0] = Asu[m * ASTR + k0];
                af[mt][1] = Asu[(m + 8) * ASTR + k0];
                af[mt][2] = Asu[m * ASTR + k0 + 4];
                af[mt][3] = Asu[(m + 8) * ASTR + k0 + 4];
            }
#pragma unroll
            for (int nt = 0; nt < 4; nt++) {
                const int n = 32 * warp_n + 8 * nt + gid;
                bf[nt][0] = Bsu[n * ASTR + k0];
                bf[nt][1] = Bsu[n * ASTR + k0 + 4];
            }
#pragma unroll
            for (int mt = 0; mt < 4; mt++)
#pragma unroll
                for (int nt = 0; nt < 4; nt++)
                    mma_tf32_16x8x8(acc[mt][nt][0], acc[mt][nt][1],
                                    acc[mt][nt][2], acc[mt][nt][3],
                                    af[mt][0], af[mt][1], af[mt][2], af[mt][3],
                                    bf[nt][0], bf[nt][1]);
        }
        __syncthreads();
        if (nxt) { sts(); __syncthreads(); }
    }

#pragma unroll
    for (int nt = 0; nt < 4; nt++) {
        const int col = n0 + 32 * warp_n + 8 * nt + 2 * qid;
        float2 badd = make_float2(0.f, 0.f);
        if (HAS_BIAS) badd = *(const float2*)&bias[col];
#pragma unroll
        for (int mt = 0; mt < 4; mt++) {
            const int row = m0 + 64 * warp_m + 16 * mt + gid;
            float2 v0 = make_float2(acc[mt][nt][0] + badd.x, acc[mt][nt][1] + badd.y);
            float2 v1 = make_float2(acc[mt][nt][2] + badd.x, acc[mt][nt][3] + badd.y);
            *(float2*)&C[(size_t)row * N + col]       = v0;
            *(float2*)&C[(size_t)(row + 8) * N + col] = v1;
        }
    }
}

// ---------------------------------------------------------------------------
// Flash attention via mma.sync tf32.
// Block: 256 thr / 8 warps, 128 queries; key tiles of 64.
// Warp w owns Q/P rows 16w..16w+15 (stats quad-local, Ps warp-private).
// smem (uint words, stride 68): Ps[128][68], Ks[64][68] ([key][d]),
// Vt[64][68] ([d][key]).  Q fragments persist in registers, scaled by SCALE.
// ---------------------------------------------------------------------------
constexpr int AT_PS = 0, AT_KS = 8704, AT_VT = 13056;
constexpr int ATTN_SMEM = 17408 * 4;   // 69632 B

__global__ __launch_bounds__(256) void attn_mma_kernel(
    const float* __restrict__ qkv, float* __restrict__ out)
{
    extern __shared__ uint32_t sm[];
    uint32_t* Ps = sm + AT_PS;
    uint32_t* Ks = sm + AT_KS;
    uint32_t* Vt = sm + AT_VT;
    float* PsF = (float*)Ps;

    const int tid = threadIdx.x, wid = tid >> 5, lane = tid & 31;
    const int gid = lane >> 2, qid = lane & 3;
    const int b = blockIdx.z, h = blockIdx.y;
    const int q0 = blockIdx.x * 128;

    const float* qb = qkv + (size_t)b * cfg::S * 3072 + h * cfg::HD;
    const float* kb = qb + cfg::D;
    const float* vb = qb + 2 * cfg::D;

    // ---- stage Q (pre-scaled) through Ps, pick up persistent fragments ----
    {
        const int r = tid >> 1, cb = (tid & 1) * 32;
        const float* qrow = qb + (size_t)(q0 + r) * 3072 + cb;
#pragma unroll
        for (int i = 0; i < 8; i++) {
            float4 v = *(const float4*)(qrow + 4 * i);
            float4 s = make_float4(v.x * cfg::SCALE, v.y * cfg::SCALE,
                                   v.z * cfg::SCALE, v.w * cfg::SCALE);
            *(float4*)&PsF[r * 68 + cb + 4 * i] = s;
        }
    }
    __syncthreads();

    const int rw = 16 * wid + gid;
    uint32_t qf[8][4];
#pragma unroll
    for (int kk = 0; kk < 8; kk++) {
        qf[kk][0] = f2tf32(PsF[rw * 68 + 8 * kk + qid]);
        qf[kk][1] = f2tf32(PsF[(rw + 8) * 68 + 8 * kk + qid]);
        qf[kk][2] = f2tf32(PsF[rw * 68 + 8 * kk + qid + 4]);
        qf[kk][3] = f2tf32(PsF[(rw + 8) * 68 + 8 * kk + qid + 4]);
    }

    // ---- K/V tile prefetch registers ----
    const int kr = tid >> 2, kc4 = (tid & 3) * 16;
    float4 kreg[4], vreg[4];
    const float* krow0 = kb + (size_t)kr * 3072 + kc4;
    const float* vrow0 = vb + (size_t)kr * 3072 + kc4;
    auto ldg_tile = [&](int s0) {
#pragma unroll
        for (int i = 0; i < 4; i++) {
            kreg[i] = *(const float4*)(krow0 + (size_t)s0 * 3072 + 4 * i);
            vreg[i] = *(const float4*)(vrow0 + (size_t)s0 * 3072 + 4 * i);
        }
    };
    ldg_tile(0);

    float o[8][4];
#pragma unroll
    for (int nt = 0; nt < 8; nt++)
#pragma unroll
        for (int r = 0; r < 4; r++) o[nt][r] = 0.f;
    float m0 = -1e30f, m1 = -1e30f, l0 = 0.f, l1 = 0.f;

    for (int t = 0; t < cfg::S / 64; ++t) {
        __syncthreads();   // prior iter done reading Ks/Vt
        // K tile -> Ks[key][d] (tf32 bits)
#pragma unroll
        for (int i = 0; i < 4; i++) {
            uint4 u;
            u.x = f2tf32(kreg[i].x); u.y = f2tf32(kreg[i].y);
            u.z = f2tf32(kreg[i].z); u.w = f2tf32(kreg[i].w);
            *(uint4*)&Ks[kr * 68 + kc4 + 4 * i] = u;
        }
        // V tile transposed -> Vt[d][key], q-staggered (conflict-free)
#pragma unroll
        for (int ii = 0; ii < 4; ii++) {
            const int i = (ii + (qid >> 1)) & 3;
            const float* vf = (const float*)&vreg[i];
#pragma unroll
            for (int jj = 0; jj < 4; jj++) {
                const int j = (jj + 2 * (qid & 1)) & 3;
                Vt[(kc4 + 4 * i + j) * 68 + kr] = f2tf32(vf[j]);
            }
        }
        __syncthreads();
        if (t + 1 < cfg::S / 64) ldg_tile(64 * (t + 1));

        // ---- S = Q K^T ----
        float acc[8][4];
#pragma unroll
        for (int nt = 0; nt < 8; nt++)
#pragma unroll
            for (int r = 0; r < 4; r++) acc[nt][r] = 0.f;
#pragma unroll
        for (int kk = 0; kk < 8; kk++) {
#pragma unroll
            for (int nt = 0; nt < 8; nt++) {
                const uint32_t b0 = Ks[(8 * nt + gid) * 68 + 8 * kk + qid];
                const uint32_t b1 = Ks[(8 * nt + gid) * 68 + 8 * kk + qid + 4];
                mma_tf32_16x8x8(acc[nt][0], acc[nt][1], acc[nt][2], acc[nt][3],
                                qf[kk][0], qf[kk][1], qf[kk][2], qf[kk][3], b0, b1);
            }
        }

        // ---- online softmax (rows rw -> c0/c1, rw+8 -> c2/c3) ----
        float mx0 = -1e30f, mx1 = -1e30f;
#pragma unroll
        for (int nt = 0; nt < 8; nt++) {
            mx0 = fmaxf(mx0, fmaxf(acc[nt][0], acc[nt][1]));
            mx1 = fmaxf(mx1, fmaxf(acc[nt][2], acc[nt][3]));
        }
        mx0 = fmaxf(mx0, __shfl_xor_sync(0xffffffffu, mx0, 1));
        mx0 = fmaxf(mx0, __shfl_xor_sync(0xffffffffu, mx0, 2));
        mx1 = fmaxf(mx1, __shfl_xor_sync(0xffffffffu, mx1, 1));
        mx1 = fmaxf(mx1, __shfl_xor_sync(0xffffffffu, mx1, 2));
        const float mn0 = fmaxf(m0, mx0), mn1 = fmaxf(m1, mx1);
        const float cr0 = __expf(m0 - mn0), cr1 = __expf(m1 - mn1);
        m0 = mn0; m1 = mn1;
        float s0 = 0.f, s1 = 0.f;
#pragma unroll
        for (int nt = 0; nt < 8; nt++) {
            const float p0 = __expf(acc[nt][0] - mn0);
            const float p1 = __expf(acc[nt][1] - mn0);
            const float p2 = __expf(acc[nt][2] - mn1);
            const float p3 = __expf(acc[nt][3] - mn1);
            s0 += p0 + p1; s1 += p2 + p3;
            uint2 u0; u0.x = f2tf32(p0); u0.y = f2tf32(p1);
            uint2 u1; u1.x = f2tf32(p2); u1.y = f2tf32(p3);
            *(uint2*)&Ps[rw * 68 + 8 * nt + 2 * qid] = u0;
            *(uint2*)&Ps[(rw + 8) * 68 + 8 * nt + 2 * qid] = u1;
        }
        s0 += __shfl_xor_sync(0xffffffffu, s0, 1);
        s0 += __shfl_xor_sync(0xffffffffu, s0, 2);
        s1 += __shfl_xor_sync(0xffffffffu, s1, 1);
        s1 += __shfl_xor_sync(0xffffffffu, s1, 2);
        l0 = l0 * cr0 + s0;
        l1 = l1 * cr1 + s1;
#pragma unroll
        for (int nt = 0; nt < 8; nt++) {
            o[nt][0] *= cr0; o[nt][1] *= cr0;
            o[nt][2] *= cr1; o[nt][3] *= cr1;
        }
        __syncwarp();   // Ps rows of this warp fully written

        // ---- O += P V ----
#pragma unroll
        for (int kk = 0; kk < 8; kk++) {
            const uint32_t a0 = Ps[rw * 68 + 8 * kk + qid];
            const uint32_t a1 = Ps[(rw + 8) * 68 + 8 * kk + qid];
            const uint32_t a2 = Ps[rw * 68 + 8 * kk + qid + 4];
            const uint32_t a3 = Ps[(rw + 8) * 68 + 8 * kk + qid + 4];
#pragma unroll
            for (int nt = 0; nt < 8; nt++) {
                const uint32_t b0 = Vt[(8 * nt + gid) * 68 + 8 * kk + qid];
                const uint32_t b1 = Vt[(8 * nt + gid) * 68 + 8 * kk + qid + 4];
                mma_tf32_16x8x8(o[nt][0], o[nt][1], o[nt][2], o[nt][3],
                                a0, a1, a2, a3, b0, b1);
            }
        }
    }

    const float i0 = 1.f / l0, i1 = 1.f / l1;
    float* orow0 = out + (size_t)(b * cfg::S + q0 + rw) * cfg::D + h * cfg::HD;
    float* orow1 = orow0 + (size_t)8 * cfg::D;
#pragma unroll
    for (int nt = 0; nt < 8; nt++) {
        *(float2*)&orow0[8 * nt + 2 * qid] =
            make_float2(o[nt][0] * i0, o[nt][1] * i0);
        *(float2*)&orow1[8 * nt + 2 * qid] =
            make_float2(o[nt][2] * i1, o[nt][3] * i1);
    }
}

// ---------------------------------------------------------------------------
extern "C" void kernel_launch(void* const* d_in, const int* in_sizes, int n_in,
                              void* d_out, int out_size)
{
    const float* x    = (const float*)d_in[0];   // [2,2048,1024]
    const float* Wqkv = (const float*)d_in[1];   // [3072,1024]
    const float* Wout = (const float*)d_in[2];   // [1024,1024]
    const float* bout = (const float*)d_in[3];   // [1024]
    float* out = (float*)d_out;                  // [2,2048,1024]

    float *qkv = nullptr, *att = nullptr;
    cudaGetSymbolAddress((void**)&qkv, g_qkv);
    cudaGetSymbolAddress((void**)&att, g_att);

    cudaFuncSetAttribute(attn_mma_kernel,
                         cudaFuncAttributeMaxDynamicSharedMemorySize, ATTN_SMEM);

    dim3 blk(256);
    // 1) qkv = x @ W_qkv^T           [4096, 3072]
    gemm_mma_kernel<false><<<dim3(3 * cfg::D / 128, cfg::MTOT / 128), blk>>>(
        x, Wqkv, nullptr, qkv, cfg::MTOT, 3 * cfg::D, cfg::D);
    // 2) flash attention -> g_att    [4096, 1024]
    attn_mma_kernel<<<dim3(cfg::S / 128, cfg::H, cfg::B), blk, ATTN_SMEM>>>(qkv, att);
    // 3) out = att @ W_out^T + b
    gemm_mma_kernel<true><<<dim3(cfg::D / 128, cfg::MTOT / 128), blk>>>(
        att, Wout, bout, out, cfg::MTOT, cfg::D, cfg::D);
}